// round 2
// baseline (speedup 1.0000x reference)
#include <cuda_runtime.h>
#include <cstdint>
#include <math.h>

#define Bv   32
#define Pv   196
#define ENCv 2048
#define DECv 512
#define EMBv 512
#define ATTv 512
#define Vv   32000
#define Lv   21
#define Tv   20
#define KSv  8

// ---------------- scratch (static device globals; no allocations) ----------------
__device__ float g_enc_s[(size_t)Bv * Pv * ENCv];   // sorted encoder  (51.4 MB)
__device__ float g_att1 [(size_t)Bv * Pv * ATTv];   // att1            (12.8 MB)
__device__ float g_mean [Bv * ENCv];
__device__ float g_h    [Bv * DECv];
__device__ float g_c    [Bv * DECv];
__device__ float g_att2 [Bv * ATTv];
__device__ float g_gate [Bv * ENCv];
__device__ float g_e    [Bv * Pv];
__device__ float g_alpha[Bv * Pv];
__device__ float g_awe  [Bv * ENCv];
__device__ float g_xh   [Bv * 3072];                 // [emb | gate*awe | h]
__device__ float g_hall [(size_t)Tv * Bv * DECv];    // all h_new, (t,b,d)
__device__ float g_partA[(size_t)KSv * Bv * 2560];   // split-K partials A
__device__ float g_partB[(size_t)KSv * Bv * 2048];   // split-K partials B
__device__ int   g_sort  [Bv];
__device__ int   g_declen[Bv];

// ---------------- small helpers ----------------
__device__ __forceinline__ float sigmf(float x){ return 1.0f / (1.0f + expf(-x)); }

// stable descending argsort of lengths (matches jnp.argsort(-lens))
__global__ void k_sort(const int* __restrict__ lens)
{
    __shared__ int s[Bv];
    int b = threadIdx.x;
    s[b] = lens[b];
    __syncthreads();
    int my = s[b], rank = 0;
    for (int j = 0; j < Bv; j++) {
        int lj = s[j];
        rank += (lj > my) || (lj == my && j < b);
    }
    g_sort[rank]   = b;
    g_declen[rank] = my - 1;
}

// gather sorted encoder + per-(b,e) mean over P
__global__ void k_gather(const float* __restrict__ enc)
{
    int b = blockIdx.x;
    int e = blockIdx.y * 256 + threadIdx.x;
    int src = g_sort[b];
    const float* in = enc + (size_t)src * Pv * ENCv + e;
    float* o = g_enc_s + (size_t)b * Pv * ENCv + e;
    float s = 0.f;
    #pragma unroll 4
    for (int p = 0; p < Pv; p++) {
        float v = in[(size_t)p * ENCv];
        o[(size_t)p * ENCv] = v;
        s += v;
    }
    g_mean[b * ENCv + e] = s * (1.0f / (float)Pv);
}

// ---------------- big SGEMM: C[m,n] = sum_k A[m,k]*W[n,k] + bias[n] ----------------
// 128x128 tile, BK=8, 256 threads, 8x8 per thread. Requires M%128==0, N%128==0, K%8==0.
// mode 0: plain store C[m*N+n]
// mode 1: preds epilogue: m=(t*32+b) -> out[b*T*V + t*V + n], zero if t >= declen[b]
__global__ void __launch_bounds__(256) k_bgemm(
    const float* __restrict__ A, const float* __restrict__ W,
    const float* __restrict__ bias, float* __restrict__ C,
    int M, int N, int K, int mode)
{
    __shared__ float As[8][128];
    __shared__ float Ws[8][128];
    int tid = threadIdx.x;
    int m0 = blockIdx.y * 128, n0 = blockIdx.x * 128;
    int lr = tid >> 1, lc = (tid & 1) * 4;
    const float* Ap = A + (size_t)(m0 + lr) * K + lc;
    const float* Wp = W + (size_t)(n0 + lr) * K + lc;
    int ty = tid >> 4, tx = tid & 15;

    float acc[8][8];
    #pragma unroll
    for (int i = 0; i < 8; i++)
        #pragma unroll
        for (int j = 0; j < 8; j++) acc[i][j] = 0.f;

    float4 av = *(const float4*)(Ap);
    float4 wv = *(const float4*)(Wp);

    for (int k0 = 0; k0 < K; k0 += 8) {
        __syncthreads();
        As[lc+0][lr]=av.x; As[lc+1][lr]=av.y; As[lc+2][lr]=av.z; As[lc+3][lr]=av.w;
        Ws[lc+0][lr]=wv.x; Ws[lc+1][lr]=wv.y; Ws[lc+2][lr]=wv.z; Ws[lc+3][lr]=wv.w;
        __syncthreads();
        if (k0 + 8 < K) {
            av = *(const float4*)(Ap + k0 + 8);
            wv = *(const float4*)(Wp + k0 + 8);
        }
        #pragma unroll
        for (int k = 0; k < 8; k++) {
            float a[8], w[8];
            *(float4*)(a)     = *(const float4*)&As[k][ty*4];
            *(float4*)(a + 4) = *(const float4*)&As[k][64 + ty*4];
            *(float4*)(w)     = *(const float4*)&Ws[k][tx*4];
            *(float4*)(w + 4) = *(const float4*)&Ws[k][64 + tx*4];
            #pragma unroll
            for (int i = 0; i < 8; i++)
                #pragma unroll
                for (int j = 0; j < 8; j++)
                    acc[i][j] = fmaf(a[i], w[j], acc[i][j]);
        }
    }

    #pragma unroll
    for (int i = 0; i < 8; i++) {
        int m = m0 + ty*4 + (i & 3) + (i >> 2) * 64;
        #pragma unroll
        for (int j = 0; j < 8; j++) {
            int n = n0 + tx*4 + (j & 3) + (j >> 2) * 64;
            float v = acc[i][j] + bias[n];
            if (mode == 0) {
                C[(size_t)m * N + n] = v;
            } else {
                int t = m >> 5, b = m & 31;
                C[(size_t)b * ((size_t)Tv * Vv) + (size_t)t * Vv + n] =
                    (t < g_declen[b]) ? v : 0.f;
            }
        }
    }
}

// ---------------- small-M (M=32) split-K GEMM -> partials ----------------
// BN=128, BK=16, 256 threads, each thread 4x4. gridDim.y == KSv (K split).
// wmode 0: W1[n*K + k]
// wmode 1: k<2560 -> W1[n*2560+k] (W_ih) else W2[n*512 + (k-2560)] (W_hh)
// wmode 2: n<512  -> W1[n*512+k]  (W_da) else W2[(n-512)*512 + k]  (W_fb)
__device__ __forceinline__ const float* w_src(int wmode,
    const float* W1, const float* W2, int n, int k, int K)
{
    if (wmode == 0) return W1 + (size_t)n * K + k;
    if (wmode == 1) return (k < 2560) ? (W1 + (size_t)n * 2560 + k)
                                      : (W2 + (size_t)n * 512 + (k - 2560));
    return (n < 512) ? (W1 + (size_t)n * 512 + k)
                     : (W2 + (size_t)(n - 512) * 512 + k);
}

__global__ void __launch_bounds__(256) k_sgemm(
    const float* __restrict__ A, int K, int N, int wmode,
    const float* __restrict__ W1, const float* __restrict__ W2,
    float* __restrict__ part)
{
    __shared__ float As[16][32];
    __shared__ float Ws[16][128];
    int tid = threadIdx.x;
    int Kc = K / KSv;
    int kbase = blockIdx.y * Kc;
    int n0 = blockIdx.x * 128;
    int tym = tid >> 5, txn = tid & 31;

    float acc[4][4];
    #pragma unroll
    for (int i = 0; i < 4; i++)
        #pragma unroll
        for (int j = 0; j < 4; j++) acc[i][j] = 0.f;

    // prefetch regs
    float4 ra = make_float4(0.f,0.f,0.f,0.f);
    int am = tid >> 2, ac4 = (tid & 3) * 4;
    if (tid < 128) ra = *(const float4*)(A + (size_t)am * K + kbase + ac4);
    int n1 = n0 + (tid >> 2),           kc41 = (tid & 3) * 4;
    int n2 = n0 + ((tid + 256) >> 2),   kc42 = ((tid + 256) & 3) * 4;
    float4 rw0 = *(const float4*)w_src(wmode, W1, W2, n1, kbase + kc41, K);
    float4 rw1 = *(const float4*)w_src(wmode, W1, W2, n2, kbase + kc42, K);

    for (int kb = 0; kb < Kc; kb += 16) {
        __syncthreads();
        if (tid < 128) {
            As[ac4+0][am]=ra.x; As[ac4+1][am]=ra.y; As[ac4+2][am]=ra.z; As[ac4+3][am]=ra.w;
        }
        {
            int nr0 = tid >> 2;
            Ws[kc41+0][nr0]=rw0.x; Ws[kc41+1][nr0]=rw0.y; Ws[kc41+2][nr0]=rw0.z; Ws[kc41+3][nr0]=rw0.w;
            int nr1 = (tid + 256) >> 2;
            Ws[kc42+0][nr1]=rw1.x; Ws[kc42+1][nr1]=rw1.y; Ws[kc42+2][nr1]=rw1.z; Ws[kc42+3][nr1]=rw1.w;
        }
        __syncthreads();
        if (kb + 16 < Kc) {
            int kn = kbase + kb + 16;
            if (tid < 128) ra = *(const float4*)(A + (size_t)am * K + kn + ac4);
            rw0 = *(const float4*)w_src(wmode, W1, W2, n1, kn + kc41, K);
            rw1 = *(const float4*)w_src(wmode, W1, W2, n2, kn + kc42, K);
        }
        #pragma unroll
        for (int k = 0; k < 16; k++) {
            float a[4], w[4];
            *(float4*)a = *(const float4*)&As[k][tym*4];
            *(float4*)w = *(const float4*)&Ws[k][txn*4];
            #pragma unroll
            for (int i = 0; i < 4; i++)
                #pragma unroll
                for (int j = 0; j < 4; j++)
                    acc[i][j] = fmaf(a[i], w[j], acc[i][j]);
        }
    }

    float* pp = part + (size_t)blockIdx.y * Bv * N;
    #pragma unroll
    for (int i = 0; i < 4; i++) {
        int m = tym*4 + i;
        #pragma unroll
        for (int j = 0; j < 4; j++)
            pp[(size_t)m * N + n0 + txn*4 + j] = acc[i][j];
    }
}

// generic split-K reduce (for h0/c0)
__global__ void k_red(float* __restrict__ dest, const float* __restrict__ bias, int N)
{
    int idx = blockIdx.x * 256 + threadIdx.x;
    int b = idx / N, n = idx - b * N;
    float s = bias[n];
    #pragma unroll
    for (int ks = 0; ks < KSv; ks++) s += g_partA[((size_t)ks * Bv + b) * N + n];
    dest[idx] = s;
}

// reduce for att2 (+bias) and gate (sigmoid(+bias))
__global__ void k_redA(const float* __restrict__ b_da, const float* __restrict__ b_fb)
{
    int idx = blockIdx.x * 256 + threadIdx.x;     // 32*2560
    int b = idx / 2560, n = idx - b * 2560;
    float s = 0.f;
    #pragma unroll
    for (int ks = 0; ks < KSv; ks++) s += g_partA[((size_t)ks * Bv + b) * 2560 + n];
    if (n < 512) {
        g_att2[b * 512 + n] = s + b_da[n];
    } else {
        int j = n - 512;
        g_gate[b * ENCv + j] = sigmf(s + b_fb[j]);
    }
}

// e[b,p] = dot( relu(att1[b,p,:] + att2[b,:]), w_fa )  (b_fa dropped: softmax shift-invariant)
__global__ void __launch_bounds__(256) k_e(const float* __restrict__ wfa)
{
    __shared__ float s2[ATTv];
    __shared__ float sw[ATTv];
    int b = blockIdx.x, tid = threadIdx.x;
    for (int i = tid; i < ATTv; i += 256) { s2[i] = g_att2[b * ATTv + i]; sw[i] = wfa[i]; }
    __syncthreads();
    int w = tid >> 5, lane = tid & 31;
    int p = blockIdx.y * 8 + w;
    if (p >= Pv) return;
    const float* a1 = g_att1 + ((size_t)b * Pv + p) * ATTv;
    float s = 0.f;
    #pragma unroll
    for (int it = 0; it < 4; it++) {
        int k = it * 128 + lane * 4;
        float4 v  = *(const float4*)(a1 + k);
        float4 t2 = *(const float4*)(s2 + k);
        float4 wf = *(const float4*)(sw + k);
        s += fmaxf(v.x + t2.x, 0.f) * wf.x + fmaxf(v.y + t2.y, 0.f) * wf.y
           + fmaxf(v.z + t2.z, 0.f) * wf.z + fmaxf(v.w + t2.w, 0.f) * wf.w;
    }
    #pragma unroll
    for (int off = 16; off; off >>= 1) s += __shfl_xor_sync(0xffffffffu, s, off);
    if (lane == 0) g_e[b * Pv + p] = s;
}

// softmax over p, write alpha scratch + masked alphas output
__global__ void __launch_bounds__(256) k_softmax(float* __restrict__ out_alpha, int t)
{
    __shared__ float red[256];
    int b = blockIdx.x, tid = threadIdx.x;
    float v = (tid < Pv) ? g_e[b * Pv + tid] : -3.4e38f;
    red[tid] = v; __syncthreads();
    for (int s = 128; s; s >>= 1) { if (tid < s) red[tid] = fmaxf(red[tid], red[tid + s]); __syncthreads(); }
    float mx = red[0]; __syncthreads();
    float ex = (tid < Pv) ? expf(v - mx) : 0.f;
    red[tid] = ex; __syncthreads();
    for (int s = 128; s; s >>= 1) { if (tid < s) red[tid] += red[tid + s]; __syncthreads(); }
    float inv = 1.0f / red[0];
    if (tid < Pv) {
        float a = ex * inv;
        g_alpha[b * Pv + tid] = a;
        out_alpha[(size_t)b * Tv * Pv + (size_t)t * Pv + tid] = (t < g_declen[b]) ? a : 0.f;
    }
}

// awe[b,e] = sum_p alpha[b,p] * enc_s[b,p,e]
__global__ void k_awe()
{
    __shared__ float sal[Pv];
    int b = blockIdx.x, tid = threadIdx.x;
    if (tid < Pv) sal[tid] = g_alpha[b * Pv + tid];
    __syncthreads();
    int e = blockIdx.y * 256 + tid;
    const float* ep = g_enc_s + (size_t)b * Pv * ENCv + e;
    float s = 0.f;
    #pragma unroll 4
    for (int p = 0; p < Pv; p++) s += sal[p] * ep[(size_t)p * ENCv];
    g_awe[b * ENCv + e] = s;
}

// build xh = [emb_W[cap], gate*awe, h]
__global__ void k_xbuild(const int* __restrict__ caps, const float* __restrict__ embW, int t)
{
    int b = blockIdx.x, tid = threadIdx.x;
    int cap = caps[g_sort[b] * Lv + t];
    const float* er = embW + (size_t)cap * EMBv;
    float* x = g_xh + b * 3072;
    for (int j = tid; j < 3072; j += 256) {
        float v;
        if (j < 512)       v = er[j];
        else if (j < 2560) v = g_gate[b * ENCv + (j - 512)] * g_awe[b * ENCv + (j - 512)];
        else               v = g_h[b * DECv + (j - 2560)];
        x[j] = v;
    }
}

// reduce split-K LSTM gates + pointwise LSTM + masked state update
__global__ void k_lstm(const float* __restrict__ b_ih, const float* __restrict__ b_hh, int t)
{
    int idx = blockIdx.x * 256 + threadIdx.x;   // Bv*DECv = 16384
    int b = idx >> 9, j = idx & 511;
    float gi = b_ih[j]        + b_hh[j];
    float gf = b_ih[512 + j]  + b_hh[512 + j];
    float gg = b_ih[1024 + j] + b_hh[1024 + j];
    float go = b_ih[1536 + j] + b_hh[1536 + j];
    #pragma unroll
    for (int ks = 0; ks < KSv; ks++) {
        const float* pp = g_partB + ((size_t)ks * Bv + b) * 2048;
        gi += pp[j]; gf += pp[512 + j]; gg += pp[1024 + j]; go += pp[1536 + j];
    }
    float cn = sigmf(gf) * g_c[idx] + sigmf(gi) * tanhf(gg);
    float hn = sigmf(go) * tanhf(cn);
    g_hall[((size_t)t * Bv + b) * DECv + j] = hn;
    if (t < g_declen[b]) { g_h[idx] = hn; g_c[idx] = cn; }
}

// ---------------- host launcher ----------------
extern "C" void kernel_launch(void* const* d_in, const int* in_sizes, int n_in,
                              void* d_out, int out_size)
{
    const float* enc  = (const float*)d_in[0];
    const int*   caps = (const int*)  d_in[1];
    const int*   lens = (const int*)  d_in[2];
    const float* embW = (const float*)d_in[3];
    const float* W_ea = (const float*)d_in[4];
    const float* b_ea = (const float*)d_in[5];
    const float* W_da = (const float*)d_in[6];
    const float* b_da = (const float*)d_in[7];
    const float* w_fa = (const float*)d_in[8];
    // d_in[9] = b_fa (unused: softmax shift-invariant)
    const float* W_ih = (const float*)d_in[10];
    const float* b_ih = (const float*)d_in[11];
    const float* W_hh = (const float*)d_in[12];
    const float* b_hh = (const float*)d_in[13];
    const float* W_h0 = (const float*)d_in[14];
    const float* b_h0 = (const float*)d_in[15];
    const float* W_c0 = (const float*)d_in[16];
    const float* b_c0 = (const float*)d_in[17];
    const float* W_fb = (const float*)d_in[18];
    const float* b_fb = (const float*)d_in[19];
    const float* W_fc = (const float*)d_in[20];
    const float* b_fc = (const float*)d_in[21];

    float* out       = (float*)d_out;
    float* out_alpha = out + (size_t)Bv * Tv * Vv;

    void* p;
    float *enc_s, *att1, *mean, *h, *c, *xh, *hall, *partA, *partB;
    cudaGetSymbolAddress(&p, g_enc_s); enc_s = (float*)p;
    cudaGetSymbolAddress(&p, g_att1);  att1  = (float*)p;
    cudaGetSymbolAddress(&p, g_mean);  mean  = (float*)p;
    cudaGetSymbolAddress(&p, g_h);     h     = (float*)p;
    cudaGetSymbolAddress(&p, g_c);     c     = (float*)p;
    cudaGetSymbolAddress(&p, g_xh);    xh    = (float*)p;
    cudaGetSymbolAddress(&p, g_hall);  hall  = (float*)p;
    cudaGetSymbolAddress(&p, g_partA); partA = (float*)p;
    cudaGetSymbolAddress(&p, g_partB); partB = (float*)p;

    // setup
    k_sort<<<1, Bv>>>(lens);
    k_gather<<<dim3(Bv, ENCv / 256), 256>>>(enc);
    // att1 = enc_s @ W_ea.T + b_ea     (6272 x 512, K=2048)
    k_bgemm<<<dim3(ATTv / 128, (Bv * Pv) / 128), 256>>>(enc_s, W_ea, b_ea, att1,
                                                        Bv * Pv, ATTv, ENCv, 0);
    // h0, c0
    k_sgemm<<<dim3(DECv / 128, KSv), 256>>>(mean, ENCv, DECv, 0, W_h0, nullptr, partA);
    k_red<<<(Bv * DECv) / 256, 256>>>(h, b_h0, DECv);
    k_sgemm<<<dim3(DECv / 128, KSv), 256>>>(mean, ENCv, DECv, 0, W_c0, nullptr, partA);
    k_red<<<(Bv * DECv) / 256, 256>>>(c, b_c0, DECv);

    for (int t = 0; t < Tv; t++) {
        // att2 (512) + gate (2048) fused GEMM from h, K=512
        k_sgemm<<<dim3(2560 / 128, KSv), 256>>>(h, DECv, 2560, 2, W_da, W_fb, partA);
        k_redA<<<(Bv * 2560) / 256, 256>>>(b_da, b_fb);
        // attention energies + softmax + awe
        k_e<<<dim3(Bv, 25), 256>>>(w_fa);
        k_softmax<<<Bv, 256>>>(out_alpha, t);
        k_awe<<<dim3(Bv, ENCv / 256), 256>>>();
        // LSTM input build + fused [x|h] GEMM, K=3072
        k_xbuild<<<Bv, 256>>>(caps, embW, t);
        k_sgemm<<<dim3(2048 / 128, KSv), 256>>>(xh, 3072, 2048, 1, W_ih, W_hh, partB);
        k_lstm<<<(Bv * DECv) / 256, 256>>>(b_ih, b_hh, t);
    }

    // predictions: (T*B) x V GEMM with mask+scatter epilogue
    k_bgemm<<<dim3(Vv / 128, (Tv * Bv) / 128), 256>>>(hall, W_fc, b_fc, out,
                                                      Tv * Bv, Vv, DECv, 1);
}